// round 16
// baseline (speedup 1.0000x reference)
#include <cuda_runtime.h>
#include <math.h>
#include <stdint.h>

#define Bz 32
#define Sz 4
#define Vz 20000
#define V4z 5000
#define Hz 512
#define Dz 2048
#define BEAMz 5
#define Nz 640            // B*S*BEAM
#define Tz 20
#define KD 512
#define VNf (-1e20f)

// ---------------- device scratch (static, no allocation; 16B-aligned for vector loads) ----------------
__device__ __align__(16) float g_logits[Nz * Vz];            // 51.2 MB
__device__ __align__(16) float g_h[Nz * Hz];
__device__ __align__(16) float g_hnew[Nz * Hz];
__device__ __align__(16) float g_imgproj[Bz * Hz];
__device__ float g_rowm[Nz];
__device__ float g_rowL[Nz];
__device__ float g_candv[Bz * Sz * Sz * BEAMz * BEAMz];   // 12800
__device__ int   g_candc[Bz * Sz * Sz * BEAMz * BEAMz];
__device__ float g_lastlp[2][Nz];
__device__ int   g_preds[Tz * Nz];
__device__ int   g_bps[(Tz - 1) * Nz];

// input-identity globals, set by k_classify
__device__ const unsigned char* g_pMask;
__device__ const float*         g_pEmb;
__device__ const float*         g_pWout;
__device__ int                  g_maskmode;   // 0 = 32-bit words nonzero, 1 = packed bytes

__device__ __forceinline__ float neg_inf() { return __int_as_float(0xff800000); }
__device__ __forceinline__ int clampV(int t) { return t < 0 ? 0 : (t >= Vz ? Vz - 1 : t); }

// ---------------- classify the three 10.24M-element inputs ----------------
// mask = the boolean-valued one; the remaining two keep order (emb, W_out) unless
// mask is last, in which case preceding pair is (W_out, emb) -> swap.
__global__ void k_classify(const void* c0, const void* c1, const void* c2,
                           long long s0, long long s1, long long s2, int forced) {
    __shared__ int flags[3][3];   // [cand][boolWord, boolFloat, boolByte]
    const void* cands[3] = {c0, c1, c2};
    long long sz[3] = {s0, s1, s2};
    int warp = threadIdx.x >> 5, lane = threadIdx.x & 31;
    if (warp < 3) {
        const unsigned int* p = (const unsigned int*)cands[warp];
        long long nw = sz[warp] / 4; if (nw > 4096) nw = 4096;
        bool bw = true, bf = true, bb = true;
        for (long long i = lane; i < nw; i += 32) {
            unsigned int w = p[i];
            if (!(w == 0u || w == 1u)) bw = false;
            if (!(w == 0u || w == 0x3F800000u)) bf = false;
            if (((w & 0xFFu) > 1u) || (((w >> 8) & 0xFFu) > 1u) ||
                (((w >> 16) & 0xFFu) > 1u) || (((w >> 24) & 0xFFu) > 1u)) bb = false;
        }
        bw = __all_sync(0xffffffffu, bw);
        bf = __all_sync(0xffffffffu, bf);
        bb = __all_sync(0xffffffffu, bb);
        if (lane == 0) { flags[warp][0] = bw; flags[warp][1] = bf; flags[warp][2] = bb; }
    }
    __syncthreads();
    if (threadIdx.x == 0) {
        int mi = forced;
        if (mi < 0) {
            for (int c = 0; c < 3; c++)
                if (flags[c][0] | flags[c][1] | flags[c][2]) { mi = c; break; }
        }
        if (mi < 0) mi = 0;
        g_pMask = (const unsigned char*)cands[mi];
        g_maskmode = (flags[mi][0] | flags[mi][1]) ? 0 : 1;
        int e, wv;
        if (mi == 0)      { e = 1; wv = 2; }
        else if (mi == 1) { e = 0; wv = 2; }
        else              { e = 1; wv = 0; }
        g_pEmb  = (const float*)cands[e];
        g_pWout = (const float*)cands[wv];
    }
}

// mask helpers
__device__ __forceinline__ const unsigned char* mask_row(size_t rowElems, int mode) {
    return g_pMask + (mode == 0 ? rowElems * 4 : rowElems);
}
__device__ __forceinline__ void load_mask4(const unsigned char* mrow, int i, int mode,
                                           int& m0, int& m1, int& m2, int& m3) {
    if (mode == 0) {
        uint4 mk = ((const uint4*)mrow)[i];
        m0 = mk.x != 0u; m1 = mk.y != 0u; m2 = mk.z != 0u; m3 = mk.w != 0u;
    } else {
        unsigned int w = ((const unsigned int*)mrow)[i];
        m0 = (w & 0xFFu) != 0u; m1 = (w & 0xFF00u) != 0u;
        m2 = (w & 0xFF0000u) != 0u; m3 = (w & 0xFF000000u) != 0u;
    }
}
__device__ __forceinline__ int load_mask1(const unsigned char* mrow, int v, int mode) {
    if (mode == 0) return ((const unsigned int*)mrow)[v] != 0u;
    return mrow[v] != 0;
}

// ---------------- stable top-5 (value desc, index asc) ----------------
struct Top5 { float v0, v1, v2, v3, v4; int i0, i1, i2, i3, i4; };

__device__ __forceinline__ void top5_init(Top5& t) {
    t.v0 = t.v1 = t.v2 = t.v3 = t.v4 = neg_inf();
    t.i0 = t.i1 = t.i2 = t.i3 = t.i4 = 0x7fffffff;
}
__device__ __forceinline__ void top5_insert(Top5& t, float x, int idx) {
    if (x > t.v4) {
        bool g3 = x > t.v3, g2 = x > t.v2, g1 = x > t.v1, g0 = x > t.v0;
        t.v4 = g3 ? t.v3 : x; t.i4 = g3 ? t.i3 : idx;
        if (g3) {
            t.v3 = g2 ? t.v2 : x; t.i3 = g2 ? t.i2 : idx;
            if (g2) {
                t.v2 = g1 ? t.v1 : x; t.i2 = g1 ? t.i1 : idx;
                if (g1) {
                    t.v1 = g0 ? t.v0 : x; t.i1 = g0 ? t.i0 : idx;
                    if (g0) { t.v0 = x; t.i0 = idx; }
                }
            }
        }
    }
}
__device__ __forceinline__ float t5v(const Top5& t, int p) {
    return p == 0 ? t.v0 : p == 1 ? t.v1 : p == 2 ? t.v2 : p == 3 ? t.v3 : p == 4 ? t.v4 : neg_inf();
}
__device__ __forceinline__ int t5i(const Top5& t, int p) {
    return p == 0 ? t.i0 : p == 1 ? t.i1 : p == 2 ? t.i2 : p == 3 ? t.i3 : p == 4 ? t.i4 : 0x7fffffff;
}
__device__ __forceinline__ void warp_top5_merge(const Top5& T, int lane, float* ov, int* oi) {
    int pos = 0;
#pragma unroll
    for (int r = 0; r < 5; r++) {
        float myv = t5v(T, pos);
        int   myi = t5i(T, pos);
        float cv = myv; int ci = myi;
#pragma unroll
        for (int off = 16; off > 0; off >>= 1) {
            float xv = __shfl_xor_sync(0xffffffffu, cv, off);
            int   xi = __shfl_xor_sync(0xffffffffu, ci, off);
            if (xv > cv || (xv == cv && xi < ci)) { cv = xv; ci = xi; }
        }
        ov[r] = cv; oi[r] = ci;
        if (myi == ci) pos++;
    }
}

// ---------------- small kernels (globals referenced in DEVICE code only) ----------------
__global__ void k_imgproj(const float* __restrict__ img, const float* __restrict__ W_im) {
    int b = blockIdx.x, h = threadIdx.x;
    float s = 0.f;
    for (int d = 0; d < Dz; d++) s = fmaf(img[b * Dz + d], W_im[d * Hz + h], s);
    g_imgproj[b * Hz + h] = s;
}

__global__ void k_inith(const int* __restrict__ startp) {
    int b = blockIdx.x, h = threadIdx.x;
    const float* emb = g_pEmb;
    int tok = clampV(startp[b]);
    g_hnew[b * Hz + h] = tanhf(emb[(size_t)tok * Hz + h] + g_imgproj[b * Hz + h]);
}

__global__ void k_expand() {
    int row = blockIdx.x;                   // 0..639
    int b = row / (Sz * BEAMz);
    float4 v = ((const float4*)(g_hnew + (size_t)b * Hz))[threadIdx.x];
    ((float4*)(g_h + (size_t)row * Hz))[threadIdx.x] = v;
}

// ---------------- SGEMM fp32 ----------------
// A/C/toks are REAL device pointers obtained via cudaGetSymbolAddress on host.
template <int EPI, int WSEL>
__global__ void __launch_bounds__(256) sgemm(
    const float* __restrict__ A, const float* __restrict__ BmIn, float* __restrict__ C,
    int M, int N, const int* __restrict__ toks)
{
    const float* Bm = (WSEL == 1) ? g_pWout : BmIn;
    const float* emb = g_pEmb;
    const int BM = 128, BN = 128, BK = 16, TM = 8, TN = 8;
    __shared__ float As[BK][BM + 4];
    __shared__ float Bs[BK][BN + 4];
    int tid = threadIdx.x;
    int tx = tid & 15, ty = tid >> 4;
    int n0 = blockIdx.x * BN, r0 = blockIdx.y * BM;

    float acc[TM][TN];
#pragma unroll
    for (int i = 0; i < TM; i++)
#pragma unroll
        for (int j = 0; j < TN; j++) acc[i][j] = 0.f;

    for (int k0 = 0; k0 < KD; k0 += BK) {
#pragma unroll
        for (int f = tid; f < BM * (BK / 4); f += 256) {
            int row = f >> 2;
            int kq = f & 3;
            int gr = r0 + row;
            float4 v = make_float4(0.f, 0.f, 0.f, 0.f);
            if (gr < M) v = *(const float4*)(A + (size_t)gr * KD + k0 + kq * 4);
            As[kq * 4 + 0][row] = v.x;
            As[kq * 4 + 1][row] = v.y;
            As[kq * 4 + 2][row] = v.z;
            As[kq * 4 + 3][row] = v.w;
        }
#pragma unroll
        for (int f = tid; f < BK * (BN / 4); f += 256) {
            int kr = f >> 5;
            int nq = f & 31;
            int gc = n0 + nq * 4;
            float4 v = make_float4(0.f, 0.f, 0.f, 0.f);
            if (gc + 3 < N) {
                v = *(const float4*)(Bm + (size_t)(k0 + kr) * N + gc);
            } else if (gc < N) {
                v.x = Bm[(size_t)(k0 + kr) * N + gc];
                if (gc + 1 < N) v.y = Bm[(size_t)(k0 + kr) * N + gc + 1];
                if (gc + 2 < N) v.z = Bm[(size_t)(k0 + kr) * N + gc + 2];
            }
            Bs[kr][nq * 4 + 0] = v.x;
            Bs[kr][nq * 4 + 1] = v.y;
            Bs[kr][nq * 4 + 2] = v.z;
            Bs[kr][nq * 4 + 3] = v.w;
        }
        __syncthreads();
#pragma unroll
        for (int kk = 0; kk < BK; kk++) {
            float a[TM], bb[TN];
#pragma unroll
            for (int i = 0; i < TM; i++) a[i] = As[kk][ty * TM + i];
#pragma unroll
            for (int j = 0; j < TN; j++) bb[j] = Bs[kk][tx * TN + j];
#pragma unroll
            for (int i = 0; i < TM; i++)
#pragma unroll
                for (int j = 0; j < TN; j++) acc[i][j] = fmaf(a[i], bb[j], acc[i][j]);
        }
        __syncthreads();
    }
#pragma unroll
    for (int i = 0; i < TM; i++) {
        int gr = r0 + ty * TM + i;
        if (gr >= M) continue;
        int tok = 0, bb_ = 0;
        if (EPI == 1) { tok = clampV(toks[gr]); bb_ = gr / (Sz * BEAMz); }
#pragma unroll
        for (int j = 0; j < TN; j++) {
            int gc = n0 + tx * TN + j;
            if (gc >= N) continue;
            if (EPI == 0) {
                C[(size_t)gr * N + gc] = acc[i][j];
            } else {
                float val = acc[i][j] + emb[(size_t)tok * Hz + gc] + g_imgproj[bb_ * Hz + gc];
                C[(size_t)gr * N + gc] = tanhf(val);
            }
        }
    }
}

// ---------------- per-row stats: m = max, L = log(sum exp(x-m)) ----------------
__global__ void k_stats(int rows) {
    int row = blockIdx.x;
    if (row >= rows) return;
    const float4* p = (const float4*)(g_logits + (size_t)row * Vz);
    int tid = threadIdx.x;   // 128
    __shared__ float sh[4];

    float m = neg_inf();
    for (int i = tid; i < V4z; i += 128) {
        float4 x = p[i];
        m = fmaxf(m, fmaxf(fmaxf(x.x, x.y), fmaxf(x.z, x.w)));
    }
#pragma unroll
    for (int off = 16; off > 0; off >>= 1) m = fmaxf(m, __shfl_xor_sync(0xffffffffu, m, off));
    if ((tid & 31) == 0) sh[tid >> 5] = m;
    __syncthreads();
    m = fmaxf(fmaxf(sh[0], sh[1]), fmaxf(sh[2], sh[3]));
    __syncthreads();

    float s = 0.f;
    for (int i = tid; i < V4z; i += 128) {
        float4 x = p[i];
        s += expf(x.x - m) + expf(x.y - m) + expf(x.z - m) + expf(x.w - m);
    }
#pragma unroll
    for (int off = 16; off > 0; off >>= 1) s += __shfl_xor_sync(0xffffffffu, s, off);
    __syncthreads();
    if ((tid & 31) == 0) sh[tid >> 5] = s;
    __syncthreads();
    if (tid == 0) {
        g_rowm[row] = m;
        g_rowL[row] = logf(sh[0] + sh[1] + sh[2] + sh[3]);
    }
}

// ---------------- step-0 masked top-5 per (b, s) ----------------
__global__ void k_step0() {
    int w = (blockIdx.x * blockDim.x + threadIdx.x) >> 5;
    int lane = threadIdx.x & 31;
    if (w >= Bz * Sz) return;
    int b = w >> 2, s = w & 3;
    int mode = g_maskmode;
    const float4* lr4 = (const float4*)(g_logits + (size_t)b * Vz);
    const unsigned char* mrow = mask_row(((size_t)(b * Sz + 0) * Sz + s) * Vz, mode);
    float m = g_rowm[b], L = g_rowL[b];

    Top5 T; top5_init(T);
    for (int i = lane; i < V4z; i += 32) {
        float4 x = lr4[i];
        int m0, m1, m2, m3;
        load_mask4(mrow, i, mode, m0, m1, m2, m3);
        int base = i * 4;
        top5_insert(T, m0 ? (x.x - m) - L : VNf, base);
        top5_insert(T, m1 ? (x.y - m) - L : VNf, base + 1);
        top5_insert(T, m2 ? (x.z - m) - L : VNf, base + 2);
        top5_insert(T, m3 ? (x.w - m) - L : VNf, base + 3);
    }
    float ov[5]; int oi[5];
    warp_top5_merge(T, lane, ov, oi);
#pragma unroll
    for (int r = 0; r < 5; r++) {
        if (lane == r) {
            int row = b * (Sz * BEAMz) + s * BEAMz + r;
            g_lastlp[0][row] = ov[r];
            g_preds[0 * Nz + row] = oi[r];
        }
    }
}

// ---------------- per-step masked top-5: one warp per (b,st,ss,beam) ----------------
__global__ void k_topk(int t) {
    int w = (blockIdx.x * blockDim.x + threadIdx.x) >> 5;
    int lane = threadIdx.x & 31;
    if (w >= Bz * Sz * Sz * BEAMz) return;
    int beam = w % BEAMz;
    int ss = (w / BEAMz) % Sz;
    int stt = (w / (BEAMz * Sz)) % Sz;
    int b = w / (BEAMz * Sz * Sz);
    int mode = g_maskmode;

    int srcrow = b * (Sz * BEAMz) + ss * BEAMz + beam;
    float llp = g_lastlp[(t - 1) & 1][srcrow];
    int lastp = g_preds[(t - 1) * Nz + srcrow];
    const unsigned char* mrow = mask_row(((size_t)(b * Sz + ss) * Sz + stt) * Vz, mode);
    int o = w * BEAMz;

    if (lastp == 0) {
        if (lane == 0) {
            int m0 = load_mask1(mrow, 0, mode);
            g_candv[o + 0] = (m0 ? 0.f : VNf) + llp;
            g_candc[o + 0] = 0;
#pragma unroll
            for (int k = 1; k < 5; k++) { g_candv[o + k] = VNf + llp; g_candc[o + k] = k; }
        }
        return;
    }

    const float4* lr4 = (const float4*)(g_logits + (size_t)srcrow * Vz);
    float m = g_rowm[srcrow], L = g_rowL[srcrow];

    Top5 T; top5_init(T);
    for (int i = lane; i < V4z; i += 32) {
        float4 x = lr4[i];
        int m0, m1, m2, m3;
        load_mask4(mrow, i, mode, m0, m1, m2, m3);
        int base = i * 4;
        top5_insert(T, m0 ? (x.x - m) - L : VNf, base);
        top5_insert(T, m1 ? (x.y - m) - L : VNf, base + 1);
        top5_insert(T, m2 ? (x.z - m) - L : VNf, base + 2);
        top5_insert(T, m3 ? (x.w - m) - L : VNf, base + 3);
    }
    float ov[5]; int oi[5];
    warp_top5_merge(T, lane, ov, oi);
#pragma unroll
    for (int r = 0; r < 5; r++) {
        if (lane == r) {
            g_candv[o + r] = ov[r] + llp;
            g_candc[o + r] = oi[r];
        }
    }
}

// ---------------- combine 100 candidates per (b, st) -> 5 beams ----------------
__global__ void k_combine(int t) {
    int w = (blockIdx.x * blockDim.x + threadIdx.x) >> 5;
    int lane = threadIdx.x & 31;
    if (w >= Bz * Sz) return;
    int b = w >> 2, stt = w & 3;
    int base = (b * Sz + stt) * (Sz * BEAMz * BEAMz);

    Top5 T; top5_init(T);
    for (int f = lane; f < Sz * BEAMz * BEAMz; f += 32)
        top5_insert(T, g_candv[base + f], f);

    float ov[5]; int oi[5];
    warp_top5_merge(T, lane, ov, oi);
#pragma unroll
    for (int r = 0; r < 5; r++) {
        if (lane == r) {
            int row = b * (Sz * BEAMz) + stt * BEAMz + r;
            g_lastlp[t & 1][row] = ov[r];
            g_preds[t * Nz + row] = g_candc[base + oi[r]];
            g_bps[(t - 1) * Nz + row] = oi[r] / BEAMz;
        }
    }
}

// ---------------- gather hidden states by backpointer ----------------
__global__ void k_gather(int t) {
    int row = blockIdx.x;
    int b = row / (Sz * BEAMz);
    int bp = g_bps[(t - 1) * Nz + row];
    int src = b * (Sz * BEAMz) + bp;
    float4 v = ((const float4*)(g_hnew + (size_t)src * Hz))[threadIdx.x];
    ((float4*)(g_h + (size_t)row * Hz))[threadIdx.x] = v;
}

// ---------------- backtrack + output (float32) ----------------
__global__ void k_output(float* __restrict__ out, int wmode, int lp_off) {
    int tid = blockIdx.x * blockDim.x + threadIdx.x;
    if (tid >= Nz) return;
    int b = tid / (Sz * BEAMz);
    int col = tid % (Sz * BEAMz);

    if (wmode & 1) {
        float* op = out + (size_t)tid * Tz;
        op[Tz - 1] = (float)g_preds[(Tz - 1) * Nz + b * (Sz * BEAMz) + col];
        int bp = g_bps[(Tz - 2) * Nz + b * (Sz * BEAMz) + col];
        for (int tt = Tz - 2; tt >= 1; tt--) {
            op[tt] = (float)g_preds[tt * Nz + b * (Sz * BEAMz) + bp];
            bp = g_bps[(tt - 1) * Nz + b * (Sz * BEAMz) + bp];
        }
        op[0] = (float)g_preds[0 * Nz + b * (Sz * BEAMz) + bp];
    }
    if (wmode & 2) {
        out[lp_off + tid] = g_lastlp[(Tz - 1) & 1][tid];
    }
}

// ---------------- launch ----------------
extern "C" void kernel_launch(void* const* d_in, const int* in_sizes, int n_in,
                              void* d_out, int out_size) {
    // REAL device pointers for __device__ globals (host-side symbol decay is UB!)
    float *p_logits = nullptr, *p_h = nullptr, *p_hnew = nullptr;
    int   *p_preds = nullptr;
    cudaGetSymbolAddress((void**)&p_logits, g_logits);
    cudaGetSymbolAddress((void**)&p_h,      g_h);
    cudaGetSymbolAddress((void**)&p_hnew,   g_hnew);
    cudaGetSymbolAddress((void**)&p_preds,  g_preds);

    // ---- size-keyed input mapping ----
    int idx_start = -1, idx_img = -1, idx_wh = -1, idx_wim = -1;
    int bigs[8]; int nbig = 0;
    bool bytes_mode = false;
    for (int i = 0; i < n_in; i++) if (in_sizes[i] == 32) { idx_start = i; }
    if (idx_start < 0) {
        for (int i = 0; i < n_in; i++) if (in_sizes[i] == 128) { idx_start = i; bytes_mode = true; }
    }
    for (int i = 0; i < n_in; i++) {
        if (i == idx_start) continue;
        long long e = bytes_mode ? (long long)in_sizes[i] / 4 : (long long)in_sizes[i];
        if (e == 65536) idx_img = i;
        else if (e == 262144) idx_wh = i;
        else if (e == 1048576) idx_wim = i;
        else if (e >= 2000000 && nbig < 8) bigs[nbig++] = i;
    }
    int forced = -1;
    int ib0, ib1, ib2;
    if (idx_start < 0 || idx_img < 0 || idx_wh < 0 || idx_wim < 0 || nbig != 3) {
        idx_img = 0; idx_start = 1; idx_wh = 4; idx_wim = 5;
        ib0 = 2; ib1 = 3; ib2 = 6;
        forced = 0;
    } else {
        ib0 = bigs[0]; ib1 = bigs[1]; ib2 = bigs[2];
    }

    const float* img    = (const float*)d_in[idx_img];
    const int*   startp = (const int*)d_in[idx_start];
    const float* W_h    = (const float*)d_in[idx_wh];
    const float* W_im   = (const float*)d_in[idx_wim];
    float* out = (float*)d_out;

    long long bsz = bytes_mode ? 1 : 4;
    k_classify<<<1, 128>>>(d_in[ib0], d_in[ib1], d_in[ib2],
                           (long long)in_sizes[ib0] * bsz,
                           (long long)in_sizes[ib1] * bsz,
                           (long long)in_sizes[ib2] * bsz, forced);

    // step 0
    k_imgproj<<<Bz, Hz>>>(img, W_im);
    k_inith<<<Bz, Hz>>>(startp);
    {
        dim3 grid((Vz + 127) / 128, 1);
        sgemm<0, 1><<<grid, 256>>>(p_hnew, nullptr, p_logits, Bz, Vz, nullptr);
    }
    k_stats<<<Bz, 128>>>(Bz);
    k_step0<<<(Bz * Sz * 32 + 255) / 256, 256>>>();
    k_expand<<<Nz, 128>>>();

    for (int t = 1; t < Tz; t++) {
        {
            dim3 grid(Hz / 128, Nz / 128);    // 4 x 5
            sgemm<1, 0><<<grid, 256>>>(p_h, W_h, p_hnew, Nz, Hz, p_preds + (t - 1) * Nz);
        }
        {
            dim3 grid((Vz + 127) / 128, Nz / 128);   // 157 x 5
            sgemm<0, 1><<<grid, 256>>>(p_hnew, nullptr, p_logits, Nz, Vz, nullptr);
        }
        k_stats<<<Nz, 128>>>(Nz);
        k_topk<<<(Bz * Sz * Sz * BEAMz) / 8, 256>>>(t);
        k_combine<<<(Bz * Sz + 3) / 4, 128>>>(t);
        k_gather<<<Nz, 128>>>(t);
    }

    int wmode, lp_off;
    if (out_size >= Nz * Tz + Nz)      { wmode = 3; lp_off = Nz * Tz; }
    else if (out_size >= Nz * Tz)      { wmode = 1; lp_off = 0;       }
    else                               { wmode = 2; lp_off = 0;       }
    k_output<<<(Nz + 127) / 128, 128>>>(out, wmode, lp_off);
    (void)n_in;
}

// round 17
// speedup vs baseline: 1.6497x; 1.6497x over previous
#include <cuda_runtime.h>
#include <math.h>
#include <stdint.h>

#define Bz 32
#define Sz 4
#define Vz 20000
#define V4z 5000
#define Hz 512
#define Dz 2048
#define BEAMz 5
#define Nz 640            // B*S*BEAM
#define Tz 20
#define KD 512
#define VNf (-1e20f)

// ---------------- device scratch (static, no allocation; 16B-aligned for vector loads) ----------------
__device__ __align__(16) float g_logits[Nz * Vz];            // 51.2 MB
__device__ __align__(16) float g_h[Nz * Hz];
__device__ __align__(16) float g_hnew[Nz * Hz];
__device__ __align__(16) float g_imgproj[Bz * Hz];
__device__ float g_rowm[Nz];
__device__ float g_rowL[Nz];
__device__ float g_candv[Bz * Sz * Sz * BEAMz * BEAMz];   // 12800
__device__ int   g_candc[Bz * Sz * Sz * BEAMz * BEAMz];
__device__ float g_lastlp[2][Nz];
__device__ int   g_preds[Tz * Nz];
__device__ int   g_bps[(Tz - 1) * Nz];

// input-identity globals, set by k_classify
__device__ const unsigned char* g_pMask;
__device__ const float*         g_pEmb;
__device__ const float*         g_pWout;
__device__ int                  g_maskmode;   // 0 = 32-bit words nonzero, 1 = packed bytes

__device__ __forceinline__ float neg_inf() { return __int_as_float(0xff800000); }
__device__ __forceinline__ int clampV(int t) { return t < 0 ? 0 : (t >= Vz ? Vz - 1 : t); }

// ---------------- cp.async helpers ----------------
__device__ __forceinline__ void cpasync16(void* smem_dst, const void* gsrc, int src_bytes) {
    uint32_t s = (uint32_t)__cvta_generic_to_shared(smem_dst);
    asm volatile("cp.async.cg.shared.global [%0], [%1], 16, %2;\n"
                 :: "r"(s), "l"(gsrc), "r"(src_bytes));
}
__device__ __forceinline__ void cp_commit() { asm volatile("cp.async.commit_group;\n"); }
__device__ __forceinline__ void cp_wait1()  { asm volatile("cp.async.wait_group 1;\n"); }
__device__ __forceinline__ void cp_wait0()  { asm volatile("cp.async.wait_group 0;\n"); }

// ---------------- classify the three 10.24M-element inputs ----------------
__global__ void k_classify(const void* c0, const void* c1, const void* c2,
                           long long s0, long long s1, long long s2, int forced) {
    __shared__ int flags[3][3];   // [cand][boolWord, boolFloat, boolByte]
    const void* cands[3] = {c0, c1, c2};
    long long sz[3] = {s0, s1, s2};
    int warp = threadIdx.x >> 5, lane = threadIdx.x & 31;
    if (warp < 3) {
        const unsigned int* p = (const unsigned int*)cands[warp];
        long long nw = sz[warp] / 4; if (nw > 4096) nw = 4096;
        bool bw = true, bf = true, bb = true;
        for (long long i = lane; i < nw; i += 32) {
            unsigned int w = p[i];
            if (!(w == 0u || w == 1u)) bw = false;
            if (!(w == 0u || w == 0x3F800000u)) bf = false;
            if (((w & 0xFFu) > 1u) || (((w >> 8) & 0xFFu) > 1u) ||
                (((w >> 16) & 0xFFu) > 1u) || (((w >> 24) & 0xFFu) > 1u)) bb = false;
        }
        bw = __all_sync(0xffffffffu, bw);
        bf = __all_sync(0xffffffffu, bf);
        bb = __all_sync(0xffffffffu, bb);
        if (lane == 0) { flags[warp][0] = bw; flags[warp][1] = bf; flags[warp][2] = bb; }
    }
    __syncthreads();
    if (threadIdx.x == 0) {
        int mi = forced;
        if (mi < 0) {
            for (int c = 0; c < 3; c++)
                if (flags[c][0] | flags[c][1] | flags[c][2]) { mi = c; break; }
        }
        if (mi < 0) mi = 0;
        g_pMask = (const unsigned char*)cands[mi];
        g_maskmode = (flags[mi][0] | flags[mi][1]) ? 0 : 1;
        int e, wv;
        if (mi == 0)      { e = 1; wv = 2; }
        else if (mi == 1) { e = 0; wv = 2; }
        else              { e = 1; wv = 0; }
        g_pEmb  = (const float*)cands[e];
        g_pWout = (const float*)cands[wv];
    }
}

// mask helpers
__device__ __forceinline__ const unsigned char* mask_row(size_t rowElems, int mode) {
    return g_pMask + (mode == 0 ? rowElems * 4 : rowElems);
}
__device__ __forceinline__ void load_mask4(const unsigned char* mrow, int i, int mode,
                                           int& m0, int& m1, int& m2, int& m3) {
    if (mode == 0) {
        uint4 mk = ((const uint4*)mrow)[i];
        m0 = mk.x != 0u; m1 = mk.y != 0u; m2 = mk.z != 0u; m3 = mk.w != 0u;
    } else {
        unsigned int w = ((const unsigned int*)mrow)[i];
        m0 = (w & 0xFFu) != 0u; m1 = (w & 0xFF00u) != 0u;
        m2 = (w & 0xFF0000u) != 0u; m3 = (w & 0xFF000000u) != 0u;
    }
}
__device__ __forceinline__ int load_mask1(const unsigned char* mrow, int v, int mode) {
    if (mode == 0) return ((const unsigned int*)mrow)[v] != 0u;
    return mrow[v] != 0;
}

// ---------------- stable top-5 (value desc, index asc) ----------------
struct Top5 { float v0, v1, v2, v3, v4; int i0, i1, i2, i3, i4; };

__device__ __forceinline__ void top5_init(Top5& t) {
    t.v0 = t.v1 = t.v2 = t.v3 = t.v4 = neg_inf();
    t.i0 = t.i1 = t.i2 = t.i3 = t.i4 = 0x7fffffff;
}
__device__ __forceinline__ void top5_insert(Top5& t, float x, int idx) {
    if (x > t.v4) {
        bool g3 = x > t.v3, g2 = x > t.v2, g1 = x > t.v1, g0 = x > t.v0;
        t.v4 = g3 ? t.v3 : x; t.i4 = g3 ? t.i3 : idx;
        if (g3) {
            t.v3 = g2 ? t.v2 : x; t.i3 = g2 ? t.i2 : idx;
            if (g2) {
                t.v2 = g1 ? t.v1 : x; t.i2 = g1 ? t.i1 : idx;
                if (g1) {
                    t.v1 = g0 ? t.v0 : x; t.i1 = g0 ? t.i0 : idx;
                    if (g0) { t.v0 = x; t.i0 = idx; }
                }
            }
        }
    }
}
__device__ __forceinline__ float t5v(const Top5& t, int p) {
    return p == 0 ? t.v0 : p == 1 ? t.v1 : p == 2 ? t.v2 : p == 3 ? t.v3 : p == 4 ? t.v4 : neg_inf();
}
__device__ __forceinline__ int t5i(const Top5& t, int p) {
    return p == 0 ? t.i0 : p == 1 ? t.i1 : p == 2 ? t.i2 : p == 3 ? t.i3 : p == 4 ? t.i4 : 0x7fffffff;
}
__device__ __forceinline__ void warp_top5_merge(const Top5& T, int lane, float* ov, int* oi) {
    int pos = 0;
#pragma unroll
    for (int r = 0; r < 5; r++) {
        float myv = t5v(T, pos);
        int   myi = t5i(T, pos);
        float cv = myv; int ci = myi;
#pragma unroll
        for (int off = 16; off > 0; off >>= 1) {
            float xv = __shfl_xor_sync(0xffffffffu, cv, off);
            int   xi = __shfl_xor_sync(0xffffffffu, ci, off);
            if (xv > cv || (xv == cv && xi < ci)) { cv = xv; ci = xi; }
        }
        ov[r] = cv; oi[r] = ci;
        if (myi == ci) pos++;
    }
}

// ---------------- small kernels ----------------
__global__ void k_imgproj(const float* __restrict__ img, const float* __restrict__ W_im) {
    int b = blockIdx.x, h = threadIdx.x;
    float s = 0.f;
    for (int d = 0; d < Dz; d++) s = fmaf(img[b * Dz + d], W_im[d * Hz + h], s);
    g_imgproj[b * Hz + h] = s;
}

__global__ void k_inith(const int* __restrict__ startp) {
    int b = blockIdx.x, h = threadIdx.x;
    const float* emb = g_pEmb;
    int tok = clampV(startp[b]);
    g_hnew[b * Hz + h] = tanhf(emb[(size_t)tok * Hz + h] + g_imgproj[b * Hz + h]);
}

__global__ void k_expand() {
    int row = blockIdx.x;                   // 0..639
    int b = row / (Sz * BEAMz);
    float4 v = ((const float4*)(g_hnew + (size_t)b * Hz))[threadIdx.x];
    ((float4*)(g_h + (size_t)row * Hz))[threadIdx.x] = v;
}

// ---------------- double-buffered SGEMM fp32 (cp.async pipeline) ----------------
// C[M,N] = A[M,512] @ B[512,N].  WSEL==1: Bm = g_pWout.
// EPI==1: C = tanh(acc + emb[tok[row]][col] + imgproj[row/20][col])
// Per-thread accumulation order identical to round-16 kernel (k ascending) ->
// bit-identical results; beam decisions cannot move.
template <int EPI, int WSEL, int BM, int TM>
__global__ void __launch_bounds__(256, 2) sgemm_db(
    const float* __restrict__ A, const float* __restrict__ BmIn, float* __restrict__ C,
    int M, int N, const int* __restrict__ toks)
{
    const float* Bm = (WSEL == 1) ? g_pWout : BmIn;
    const float* emb = g_pEmb;
    const int BN = 128, BK = 16, TN = 8;
    __shared__ float As[2][BM][BK];     // row-major A tile
    __shared__ float Bs[2][BK][BN];
    int tid = threadIdx.x;
    int tx = tid & 15, ty = tid >> 4;
    int n0 = blockIdx.x * BN, r0 = blockIdx.y * BM;

    float acc[TM][TN];
#pragma unroll
    for (int i = 0; i < TM; i++)
#pragma unroll
        for (int j = 0; j < TN; j++) acc[i][j] = 0.f;

    const int NKT = KD / BK;   // 32

    // tile loader: A tile (BM x 16 floats) as BM*4 16B-chunks; B tile (16 x 128) as 512 chunks
    auto load_tiles = [&](int kt, int st) {
        int k0 = kt * BK;
#pragma unroll 2
        for (int c = tid; c < BM * 4; c += 256) {
            int row = c >> 2, kq = c & 3;
            int gr = r0 + row;
            int ok = (gr < M);
            const float* src = A + (size_t)(ok ? gr : 0) * KD + k0 + kq * 4;
            cpasync16(&As[st][row][kq * 4], src, ok ? 16 : 0);
        }
#pragma unroll 2
        for (int c = tid; c < BK * 32; c += 256) {
            int kr = c >> 5, nq = c & 31;
            int gc = n0 + nq * 4;
            int ok = (gc < N);          // N % 4 == 0 for all our shapes
            const float* src = Bm + (size_t)(k0 + kr) * N + (ok ? gc : 0);
            cpasync16(&Bs[st][kr][nq * 4], src, ok ? 16 : 0);
        }
    };

    load_tiles(0, 0);
    cp_commit();

    for (int it = 0; it < NKT; it++) {
        int st = it & 1;
        if (it + 1 < NKT) {
            load_tiles(it + 1, (it + 1) & 1);
            cp_commit();
            cp_wait1();              // current stage's group complete
        } else {
            cp_wait0();
        }
        __syncthreads();

#pragma unroll
        for (int kk = 0; kk < BK; kk++) {
            float a[TM], bb[TN];
#pragma unroll
            for (int i = 0; i < TM; i++) a[i] = As[st][ty * TM + i][kk];
#pragma unroll
            for (int j = 0; j < TN; j++) bb[j] = Bs[st][kk][tx * TN + j];
#pragma unroll
            for (int i = 0; i < TM; i++)
#pragma unroll
                for (int j = 0; j < TN; j++) acc[i][j] = fmaf(a[i], bb[j], acc[i][j]);
        }
        __syncthreads();
    }

#pragma unroll
    for (int i = 0; i < TM; i++) {
        int gr = r0 + ty * TM + i;
        if (gr >= M) continue;
        int tok = 0, bb_ = 0;
        if (EPI == 1) { tok = clampV(toks[gr]); bb_ = gr / (Sz * BEAMz); }
#pragma unroll
        for (int j = 0; j < TN; j++) {
            int gc = n0 + tx * TN + j;
            if (gc >= N) continue;
            if (EPI == 0) {
                C[(size_t)gr * N + gc] = acc[i][j];
            } else {
                float val = acc[i][j] + emb[(size_t)tok * Hz + gc] + g_imgproj[bb_ * Hz + gc];
                C[(size_t)gr * N + gc] = tanhf(val);
            }
        }
    }
}

// ---------------- per-row stats: m = max, L = log(sum exp(x-m)) ----------------
__global__ void k_stats(int rows) {
    int row = blockIdx.x;
    if (row >= rows) return;
    const float4* p = (const float4*)(g_logits + (size_t)row * Vz);
    int tid = threadIdx.x;   // 128
    __shared__ float sh[4];

    float m = neg_inf();
    for (int i = tid; i < V4z; i += 128) {
        float4 x = p[i];
        m = fmaxf(m, fmaxf(fmaxf(x.x, x.y), fmaxf(x.z, x.w)));
    }
#pragma unroll
    for (int off = 16; off > 0; off >>= 1) m = fmaxf(m, __shfl_xor_sync(0xffffffffu, m, off));
    if ((tid & 31) == 0) sh[tid >> 5] = m;
    __syncthreads();
    m = fmaxf(fmaxf(sh[0], sh[1]), fmaxf(sh[2], sh[3]));
    __syncthreads();

    float s = 0.f;
    for (int i = tid; i < V4z; i += 128) {
        float4 x = p[i];
        s += expf(x.x - m) + expf(x.y - m) + expf(x.z - m) + expf(x.w - m);
    }
#pragma unroll
    for (int off = 16; off > 0; off >>= 1) s += __shfl_xor_sync(0xffffffffu, s, off);
    __syncthreads();
    if ((tid & 31) == 0) sh[tid >> 5] = s;
    __syncthreads();
    if (tid == 0) {
        g_rowm[row] = m;
        g_rowL[row] = logf(sh[0] + sh[1] + sh[2] + sh[3]);
    }
}

// ---------------- step-0 masked top-5 per (b, s) ----------------
__global__ void k_step0() {
    int w = (blockIdx.x * blockDim.x + threadIdx.x) >> 5;
    int lane = threadIdx.x & 31;
    if (w >= Bz * Sz) return;
    int b = w >> 2, s = w & 3;
    int mode = g_maskmode;
    const float4* lr4 = (const float4*)(g_logits + (size_t)b * Vz);
    const unsigned char* mrow = mask_row(((size_t)(b * Sz + 0) * Sz + s) * Vz, mode);
    float m = g_rowm[b], L = g_rowL[b];

    Top5 T; top5_init(T);
    for (int i = lane; i < V4z; i += 32) {
        float4 x = lr4[i];
        int m0, m1, m2, m3;
        load_mask4(mrow, i, mode, m0, m1, m2, m3);
        int base = i * 4;
        top5_insert(T, m0 ? (x.x - m) - L : VNf, base);
        top5_insert(T, m1 ? (x.y - m) - L : VNf, base + 1);
        top5_insert(T, m2 ? (x.z - m) - L : VNf, base + 2);
        top5_insert(T, m3 ? (x.w - m) - L : VNf, base + 3);
    }
    float ov[5]; int oi[5];
    warp_top5_merge(T, lane, ov, oi);
#pragma unroll
    for (int r = 0; r < 5; r++) {
        if (lane == r) {
            int row = b * (Sz * BEAMz) + s * BEAMz + r;
            g_lastlp[0][row] = ov[r];
            g_preds[0 * Nz + row] = oi[r];
        }
    }
}

// ---------------- per-step masked top-5: one warp per (b,st,ss,beam) ----------------
__global__ void k_topk(int t) {
    int w = (blockIdx.x * blockDim.x + threadIdx.x) >> 5;
    int lane = threadIdx.x & 31;
    if (w >= Bz * Sz * Sz * BEAMz) return;
    int beam = w % BEAMz;
    int ss = (w / BEAMz) % Sz;
    int stt = (w / (BEAMz * Sz)) % Sz;
    int b = w / (BEAMz * Sz * Sz);
    int mode = g_maskmode;

    int srcrow = b * (Sz * BEAMz) + ss * BEAMz + beam;
    float llp = g_lastlp[(t - 1) & 1][srcrow];
    int lastp = g_preds[(t - 1) * Nz + srcrow];
    const unsigned char* mrow = mask_row(((size_t)(b * Sz + ss) * Sz + stt) * Vz, mode);
    int o = w * BEAMz;

    if (lastp == 0) {
        if (lane == 0) {
            int m0 = load_mask1(mrow, 0, mode);
            g_candv[o + 0] = (m0 ? 0.f : VNf) + llp;
            g_candc[o + 0] = 0;
#pragma unroll
            for (int k = 1; k < 5; k++) { g_candv[o + k] = VNf + llp; g_candc[o + k] = k; }
        }
        return;
    }

    const float4* lr4 = (const float4*)(g_logits + (size_t)srcrow * Vz);
    float m = g_rowm[srcrow], L = g_rowL[srcrow];

    Top5 T; top5_init(T);
    for (int i = lane; i < V4z; i += 32) {
        float4 x = lr4[i];
        int m0, m1, m2, m3;
        load_mask4(mrow, i, mode, m0, m1, m2, m3);
        int base = i * 4;
        top5_insert(T, m0 ? (x.x - m) - L : VNf, base);
        top5_insert(T, m1 ? (x.y - m) - L : VNf, base + 1);
        top5_insert(T, m2 ? (x.z - m) - L : VNf, base + 2);
        top5_insert(T, m3 ? (x.w - m) - L : VNf, base + 3);
    }
    float ov[5]; int oi[5];
    warp_top5_merge(T, lane, ov, oi);
#pragma unroll
    for (int r = 0; r < 5; r++) {
        if (lane == r) {
            g_candv[o + r] = ov[r] + llp;
            g_candc[o + r] = oi[r];
        }
    }
}

// ---------------- combine 100 candidates per (b, st) -> 5 beams ----------------
__global__ void k_combine(int t) {
    int w = (blockIdx.x * blockDim.x + threadIdx.x) >> 5;
    int lane = threadIdx.x & 31;
    if (w >= Bz * Sz) return;
    int b = w >> 2, stt = w & 3;
    int base = (b * Sz + stt) * (Sz * BEAMz * BEAMz);

    Top5 T; top5_init(T);
    for (int f = lane; f < Sz * BEAMz * BEAMz; f += 32)
        top5_insert(T, g_candv[base + f], f);

    float ov[5]; int oi[5];
    warp_top5_merge(T, lane, ov, oi);
#pragma unroll
    for (int r = 0; r < 5; r++) {
        if (lane == r) {
            int row = b * (Sz * BEAMz) + stt * BEAMz + r;
            g_lastlp[t & 1][row] = ov[r];
            g_preds[t * Nz + row] = g_candc[base + oi[r]];
            g_bps[(t - 1) * Nz + row] = oi[r] / BEAMz;
        }
    }
}

// ---------------- gather hidden states by backpointer ----------------
__global__ void k_gather(int t) {
    int row = blockIdx.x;
    int b = row / (Sz * BEAMz);
    int bp = g_bps[(t - 1) * Nz + row];
    int src = b * (Sz * BEAMz) + bp;
    float4 v = ((const float4*)(g_hnew + (size_t)src * Hz))[threadIdx.x];
    ((float4*)(g_h + (size_t)row * Hz))[threadIdx.x] = v;
}

// ---------------- backtrack + output (float32) ----------------
__global__ void k_output(float* __restrict__ out, int wmode, int lp_off) {
    int tid = blockIdx.x * blockDim.x + threadIdx.x;
    if (tid >= Nz) return;
    int b = tid / (Sz * BEAMz);
    int col = tid % (Sz * BEAMz);

    if (wmode & 1) {
        float* op = out + (size_t)tid * Tz;
        op[Tz - 1] = (float)g_preds[(Tz - 1) * Nz + b * (Sz * BEAMz) + col];
        int bp = g_bps[(Tz - 2) * Nz + b * (Sz * BEAMz) + col];
        for (int tt = Tz - 2; tt >= 1; tt--) {
            op[tt] = (float)g_preds[tt * Nz + b * (Sz * BEAMz) + bp];
            bp = g_bps[(tt - 1) * Nz + b * (Sz * BEAMz) + bp];
        }
        op[0] = (float)g_preds[0 * Nz + b * (Sz * BEAMz) + bp];
    }
    if (wmode & 2) {
        out[lp_off + tid] = g_lastlp[(Tz - 1) & 1][tid];
    }
}

// ---------------- launch ----------------
extern "C" void kernel_launch(void* const* d_in, const int* in_sizes, int n_in,
                              void* d_out, int out_size) {
    // REAL device pointers for __device__ globals (host-side symbol decay is UB!)
    float *p_logits = nullptr, *p_h = nullptr, *p_hnew = nullptr;
    int   *p_preds = nullptr;
    cudaGetSymbolAddress((void**)&p_logits, g_logits);
    cudaGetSymbolAddress((void**)&p_h,      g_h);
    cudaGetSymbolAddress((void**)&p_hnew,   g_hnew);
    cudaGetSymbolAddress((void**)&p_preds,  g_preds);

    // ---- size-keyed input mapping ----
    int idx_start = -1, idx_img = -1, idx_wh = -1, idx_wim = -1;
    int bigs[8]; int nbig = 0;
    bool bytes_mode = false;
    for (int i = 0; i < n_in; i++) if (in_sizes[i] == 32) { idx_start = i; }
    if (idx_start < 0) {
        for (int i = 0; i < n_in; i++) if (in_sizes[i] == 128) { idx_start = i; bytes_mode = true; }
    }
    for (int i = 0; i < n_in; i++) {
        if (i == idx_start) continue;
        long long e = bytes_mode ? (long long)in_sizes[i] / 4 : (long long)in_sizes[i];
        if (e == 65536) idx_img = i;
        else if (e == 262144) idx_wh = i;
        else if (e == 1048576) idx_wim = i;
        else if (e >= 2000000 && nbig < 8) bigs[nbig++] = i;
    }
    int forced = -1;
    int ib0, ib1, ib2;
    if (idx_start < 0 || idx_img < 0 || idx_wh < 0 || idx_wim < 0 || nbig != 3) {
        idx_img = 0; idx_start = 1; idx_wh = 4; idx_wim = 5;
        ib0 = 2; ib1 = 3; ib2 = 6;
        forced = 0;
    } else {
        ib0 = bigs[0]; ib1 = bigs[1]; ib2 = bigs[2];
    }

    const float* img    = (const float*)d_in[idx_img];
    const int*   startp = (const int*)d_in[idx_start];
    const float* W_h    = (const float*)d_in[idx_wh];
    const float* W_im   = (const float*)d_in[idx_wim];
    float* out = (float*)d_out;

    long long bsz = bytes_mode ? 1 : 4;
    k_classify<<<1, 128>>>(d_in[ib0], d_in[ib1], d_in[ib2],
                           (long long)in_sizes[ib0] * bsz,
                           (long long)in_sizes[ib1] * bsz,
                           (long long)in_sizes[ib2] * bsz, forced);

    // step 0 (BM=32 tile: M=32, no wasted rows)
    k_imgproj<<<Bz, Hz>>>(img, W_im);
    k_inith<<<Bz, Hz>>>(startp);
    {
        dim3 grid((Vz + 127) / 128, 1);
        sgemm_db<0, 1, 32, 2><<<grid, 256>>>(p_hnew, nullptr, p_logits, Bz, Vz, nullptr);
    }
    k_stats<<<Bz, 128>>>(Bz);
    k_step0<<<(Bz * Sz * 32 + 255) / 256, 256>>>();
    k_expand<<<Nz, 128>>>();

    for (int t = 1; t < Tz; t++) {
        {
            dim3 grid(Hz / 128, Nz / 128);    // 4 x 5
            sgemm_db<1, 0, 128, 8><<<grid, 256>>>(p_h, W_h, p_hnew, Nz, Hz, p_preds + (t - 1) * Nz);
        }
        {
            dim3 grid((Vz + 127) / 128, Nz / 128);   // 157 x 5
            sgemm_db<0, 1, 128, 8><<<grid, 256>>>(p_hnew, nullptr, p_logits, Nz, Vz, nullptr);
        }
        k_stats<<<Nz, 128>>>(Nz);
        k_topk<<<(Bz * Sz * Sz * BEAMz) / 8, 256>>>(t);
        k_combine<<<(Bz * Sz + 3) / 4, 128>>>(t);
        k_gather<<<Nz, 128>>>(t);
    }

    int wmode, lp_off;
    if (out_size >= Nz * Tz + Nz)      { wmode = 3; lp_off = Nz * Tz; }
    else if (out_size >= Nz * Tz)      { wmode = 1; lp_off = 0;       }
    else                               { wmode = 2; lp_off = 0;       }
    k_output<<<(Nz + 127) / 128, 128>>>(out, wmode, lp_off);
    (void)n_in;
}